// round 14
// baseline (speedup 1.0000x reference)
#include <cuda_runtime.h>
#include <cuda_bf16.h>
#include <math.h>
#include <cstdint>

// Problem constants
#define B_SZ   2
#define S_LEN  2048
#define D_DIM  2048
#define H_NUM  16
#define HD     128
#define M_ROWS (B_SZ * S_LEN)   // 4096

// ---------------------------------------------------------------------------
// Scratch (static device globals)
// ---------------------------------------------------------------------------
__device__ __nv_bfloat16 g_ahi[M_ROWS * D_DIM];       // x hi, later ctx hi
__device__ __nv_bfloat16 g_alo[M_ROWS * D_DIM];       // x lo, later ctx lo
__device__ __nv_bfloat16 g_w3hi[3 * D_DIM * D_DIM];   // [Wq;Wk;Wv] hi
__device__ __nv_bfloat16 g_w3lo[3 * D_DIM * D_DIM];   // [Wq;Wk;Wv] lo
__device__ __nv_bfloat16 g_whi[D_DIM * D_DIM];        // Wo hi
__device__ __nv_bfloat16 g_wlo[D_DIM * D_DIM];        // Wo lo
__device__ __nv_bfloat16 g_qh [M_ROWS * D_DIM];
__device__ __nv_bfloat16 g_ql [M_ROWS * D_DIM];
__device__ __nv_bfloat16 g_kh [M_ROWS * D_DIM];
__device__ __nv_bfloat16 g_kl [M_ROWS * D_DIM];
__device__ __nv_bfloat16 g_vh [M_ROWS * D_DIM];
__device__ __nv_bfloat16 g_vl [M_ROWS * D_DIM];
__device__ float2 g_tab[S_LEN * 64];                  // rope (cos,sin) table

// ---------------------------------------------------------------------------
// PTX helpers
// ---------------------------------------------------------------------------
__device__ __forceinline__ uint32_t smem_u32(const void* p) {
    uint32_t a;
    asm("{ .reg .u64 t; cvta.to.shared.u64 t, %1; cvt.u32.u64 %0, t; }"
        : "=r"(a) : "l"(p));
    return a;
}
__device__ __forceinline__ void cp16(uint32_t s, const void* g) {
    asm volatile("cp.async.cg.shared.global [%0], [%1], 16;" :: "r"(s), "l"(g));
}
#define CP_COMMIT() asm volatile("cp.async.commit_group;" ::: "memory")
#define CP_WAIT(n)  asm volatile("cp.async.wait_group %0;" :: "n"(n) : "memory")

__device__ __forceinline__ void ldsm_x4(uint32_t* r, uint32_t addr) {
    asm volatile("ldmatrix.sync.aligned.m8n8.x4.shared.b16 {%0,%1,%2,%3}, [%4];"
                 : "=r"(r[0]), "=r"(r[1]), "=r"(r[2]), "=r"(r[3]) : "r"(addr));
}
__device__ __forceinline__ void ldsm_x4_t(uint32_t* r, uint32_t addr) {
    asm volatile("ldmatrix.sync.aligned.m8n8.x4.trans.shared.b16 {%0,%1,%2,%3}, [%4];"
                 : "=r"(r[0]), "=r"(r[1]), "=r"(r[2]), "=r"(r[3]) : "r"(addr));
}
__device__ __forceinline__ void mma16816(float* d, const uint32_t* a,
                                         const uint32_t* b) {
    asm volatile(
        "mma.sync.aligned.m16n8k16.row.col.f32.bf16.bf16.f32 "
        "{%0,%1,%2,%3}, {%4,%5,%6,%7}, {%8,%9}, {%0,%1,%2,%3};"
        : "+f"(d[0]), "+f"(d[1]), "+f"(d[2]), "+f"(d[3])
        : "r"(a[0]), "r"(a[1]), "r"(a[2]), "r"(a[3]), "r"(b[0]), "r"(b[1]));
}
__device__ __forceinline__ float ex2(float x) {
    float y;
    asm("ex2.approx.ftz.f32 %0, %1;" : "=f"(y) : "f"(x));
    return y;
}
__device__ __forceinline__ uint32_t pk_hi(float a, float b) {
    __nv_bfloat162 t = __floats2bfloat162_rn(a, b);
    return *(uint32_t*)&t;
}
__device__ __forceinline__ uint32_t pk_lo(float a, float b, uint32_t hi) {
    __nv_bfloat162 h = *(__nv_bfloat162*)&hi;
    return pk_hi(a - __bfloat162float(h.x), b - __bfloat162float(h.y));
}

// ---------------------------------------------------------------------------
// RoPE table
// ---------------------------------------------------------------------------
__global__ void tab_kernel(float2* __restrict__ T)
{
    int idx = blockIdx.x * blockDim.x + threadIdx.x;
    if (idx >= S_LEN * 64) return;
    int s = idx >> 6;
    int i = idx & 63;
    float inv = powf(10000.f, -(float)(2 * i) / 128.f);
    float ang = (float)s * inv;
    float sv, cv;
    sincosf(ang, &sv, &cv);
    T[idx] = make_float2(cv, sv);
}

// ---------------------------------------------------------------------------
// split: fp32 -> (hi bf16, lo bf16)
// ---------------------------------------------------------------------------
__global__ void split_kernel(const float* __restrict__ X,
                             __nv_bfloat16* __restrict__ H,
                             __nv_bfloat16* __restrict__ L, int n4)
{
    int i = blockIdx.x * blockDim.x + threadIdx.x;
    if (i >= n4) return;
    float4 v = ((const float4*)X)[i];
    uint32_t h0 = pk_hi(v.x, v.y), h1 = pk_hi(v.z, v.w);
    uint32_t l0 = pk_lo(v.x, v.y, h0), l1 = pk_lo(v.z, v.w, h1);
    ((uint2*)H)[i] = make_uint2(h0, h1);
    ((uint2*)L)[i] = make_uint2(l0, l1);
}

// ---------------------------------------------------------------------------
// wsplit4: split all four weight matrices in one launch.
// ---------------------------------------------------------------------------
__global__ void wsplit4_kernel(const float* __restrict__ Wq,
                               const float* __restrict__ Wk,
                               const float* __restrict__ Wv,
                               const float* __restrict__ Wo,
                               __nv_bfloat16* __restrict__ W3H,
                               __nv_bfloat16* __restrict__ W3L,
                               __nv_bfloat16* __restrict__ WOH,
                               __nv_bfloat16* __restrict__ WOL,
                               int nw4)
{
    int i = blockIdx.x * blockDim.x + threadIdx.x;
    if (i >= 4 * nw4) return;
    int sel = i / nw4;
    int j   = i - sel * nw4;
    const float* src = (sel == 0) ? Wq : (sel == 1) ? Wk : (sel == 2) ? Wv : Wo;
    __nv_bfloat16* H = (sel < 3) ? W3H : WOH;
    __nv_bfloat16* L = (sel < 3) ? W3L : WOL;
    int o = (sel < 3) ? sel * nw4 + j : j;
    float4 v = ((const float4*)src)[j];
    uint32_t h0 = pk_hi(v.x, v.y), h1 = pk_hi(v.z, v.w);
    uint32_t l0 = pk_lo(v.x, v.y, h0), l1 = pk_lo(v.z, v.w, h1);
    ((uint2*)H)[o] = make_uint2(h0, h1);
    ((uint2*)L)[o] = make_uint2(l0, l1);
}

// ---------------------------------------------------------------------------
// HMMA bf16 split GEMM: 128x128 CTA tile, 4 warps (2x2) of 64x64, 2 CTAs/SM.
// PERSISTENT with CROSS-TILE PIPELINING: the last mainloop iteration of each
// tile prefetches the next tile's stage 0 -> no cold prologue, no wave tail.
// MODE 0: fp32 C out. MODE 1: fused QKV epilogue.
// ---------------------------------------------------------------------------
#define BM 128
#define BN 128
#define BK 32
#define PIT 40
#define TILE_B (BM * PIT * 2)        // 10240 bytes per array
#define STAGE_B (4 * TILE_B)         // 40960
#define GEMM_SMEM (2 * STAGE_B)      // 81920
#define GEMM_GRID 296                // 148 SMs x 2 CTAs

__device__ __forceinline__ void g_load_stage(
    uint32_t st, const __nv_bfloat16* __restrict__ Ah,
    const __nv_bfloat16* __restrict__ Al, const __nv_bfloat16* __restrict__ Bh,
    const __nv_bfloat16* __restrict__ Bl, int bm, int bn, int k0, int K, int tid)
{
#pragma unroll
    for (int it = 0; it < 16; it++) {
        int c = tid + it * 128;
        int arr = c >> 9;
        int r   = (c & 511) >> 2;
        int c16 = c & 3;
        uint32_t dst = st + arr * TILE_B + r * (PIT * 2) + c16 * 16;
        const __nv_bfloat16* src;
        if (arr == 0)      src = Ah + (size_t)(bm + r) * K + k0 + c16 * 8;
        else if (arr == 1) src = Al + (size_t)(bm + r) * K + k0 + c16 * 8;
        else if (arr == 2) src = Bh + (size_t)(bn + r) * K + k0 + c16 * 8;
        else               src = Bl + (size_t)(bn + r) * K + k0 + c16 * 8;
        cp16(dst, src);
    }
}

template <int MODE>
__global__ void __launch_bounds__(128, 2)
mma_gemm_kernel(const __nv_bfloat16* __restrict__ Ah,
                const __nv_bfloat16* __restrict__ Al,
                const __nv_bfloat16* __restrict__ Bh,
                const __nv_bfloat16* __restrict__ Bl,
                float* __restrict__ C,
                __nv_bfloat16* __restrict__ QH, __nv_bfloat16* __restrict__ QL,
                __nv_bfloat16* __restrict__ KH, __nv_bfloat16* __restrict__ KL,
                __nv_bfloat16* __restrict__ VH, __nv_bfloat16* __restrict__ VL,
                const float2* __restrict__ tab,
                int M, int N, int K, int ntiles, int nxt)
{
    extern __shared__ char smem[];
    const uint32_t sb = smem_u32(smem);

    const int tid  = threadIdx.x;
    const int wid  = tid >> 5;
    const int lane = tid & 31;
    const int wy   = wid >> 1;
    const int wx   = wid & 1;

    const int a_row = wy * 64 + (lane & 15);
    const int a_kof = (lane >> 4) * 8;
    const int b_row = wx * 64 + (lane & 7) + ((lane >> 4) << 3);
    const int b_kof = ((lane >> 3) & 1) * 8;
    const int er = lane >> 2;
    const int ec = (lane & 3) * 2;

    const int nk = K / BK;

    int tile = blockIdx.x;
    if (tile >= ntiles) return;

    // prologue: first tile's stage 0 into buffer 0
    {
        const int bm0 = (tile / nxt) * BM;
        const int bn0 = (tile - (tile / nxt) * nxt) * BN;
        g_load_stage(sb, Ah, Al, Bh, Bl, bm0, bn0, 0, K, tid);
        CP_COMMIT();
    }
    int buf = 0;

    while (tile < ntiles) {
        const int bm = (tile / nxt) * BM;
        const int bn = (tile - (tile / nxt) * nxt) * BN;
        const int next_tile = tile + gridDim.x;

        float acc[4][8][4];
#pragma unroll
        for (int mt = 0; mt < 4; mt++)
#pragma unroll
            for (int nt = 0; nt < 8; nt++)
#pragma unroll
                for (int e = 0; e < 4; e++) acc[mt][nt][e] = 0.f;

        for (int i = 0; i < nk; i++) {
            // issue next load: next stage of this tile, or next tile's stage 0
            bool loaded = false;
            if (i + 1 < nk) {
                g_load_stage(sb + (buf ^ 1) * STAGE_B,
                             Ah, Al, Bh, Bl, bm, bn, (i + 1) * BK, K, tid);
                loaded = true;
            } else if (next_tile < ntiles) {
                const int nbm = (next_tile / nxt) * BM;
                const int nbn = (next_tile - (next_tile / nxt) * nxt) * BN;
                g_load_stage(sb + (buf ^ 1) * STAGE_B,
                             Ah, Al, Bh, Bl, nbm, nbn, 0, K, tid);
                loaded = true;
            }
            if (loaded) { CP_COMMIT(); CP_WAIT(1); }
            else        { CP_WAIT(0); }
            __syncthreads();

            const uint32_t st  = sb + buf * STAGE_B;
            const uint32_t sAh = st;
            const uint32_t sAl = st + TILE_B;
            const uint32_t sBh = st + 2 * TILE_B;
            const uint32_t sBl = st + 3 * TILE_B;

#pragma unroll
            for (int ks = 0; ks < 2; ks++) {
                const int kk = ks * 16;
                uint32_t fah[4][4], fal[4][4], fbh[4][4], fbl[4][4];
#pragma unroll
                for (int mt = 0; mt < 4; mt++) {
                    uint32_t off = (uint32_t)(a_row + mt * 16) * (PIT * 2)
                                   + (uint32_t)(kk + a_kof) * 2;
                    ldsm_x4(fah[mt], sAh + off);
                    ldsm_x4(fal[mt], sAl + off);
                }
#pragma unroll
                for (int np = 0; np < 4; np++) {
                    uint32_t off = (uint32_t)(b_row + np * 16) * (PIT * 2)
                                   + (uint32_t)(kk + b_kof) * 2;
                    ldsm_x4(fbh[np], sBh + off);
                    ldsm_x4(fbl[np], sBl + off);
                }
#pragma unroll
                for (int mt = 0; mt < 4; mt++)
#pragma unroll
                    for (int np = 0; np < 4; np++) {
                        mma16816(acc[mt][2 * np],     fah[mt], fbh[np]);
                        mma16816(acc[mt][2 * np + 1], fah[mt], fbh[np] + 2);
                        mma16816(acc[mt][2 * np],     fah[mt], fbl[np]);
                        mma16816(acc[mt][2 * np + 1], fah[mt], fbl[np] + 2);
                        mma16816(acc[mt][2 * np],     fal[mt], fbh[np]);
                        mma16816(acc[mt][2 * np + 1], fal[mt], fbh[np] + 2);
                    }
            }
            __syncthreads();
            buf ^= 1;
        }

        // epilogue (overlaps next tile's in-flight stage-0 loads)
        if (MODE == 0) {
#pragma unroll
            for (int mt = 0; mt < 4; mt++) {
                const int r0 = bm + wy * 64 + mt * 16 + er;
#pragma unroll
                for (int nt = 0; nt < 8; nt++) {
                    const int c0 = bn + wx * 64 + nt * 8 + ec;
                    *(float2*)&C[(size_t)r0 * N + c0] =
                        make_float2(acc[mt][nt][0], acc[mt][nt][1]);
                    *(float2*)&C[(size_t)(r0 + 8) * N + c0] =
                        make_float2(acc[mt][nt][2], acc[mt][nt][3]);
                }
            }
        } else {
            const int sel = bn >> 11;             // 0=q, 1=k, 2=v (CTA-uniform)
            __nv_bfloat16* H = (sel == 0) ? QH : (sel == 1) ? KH : VH;
            __nv_bfloat16* L = (sel == 0) ? QL : (sel == 1) ? KL : VL;
#pragma unroll
            for (int mt = 0; mt < 4; mt++) {
                const int r0 = bm + wy * 64 + mt * 16 + er;
                const int r1 = r0 + 8;
#pragma unroll
                for (int nt = 0; nt < 8; nt++) {
                    const int c = (bn + wx * 64 + nt * 8 + ec) & 2047;
                    float a0 = acc[mt][nt][0], a1 = acc[mt][nt][1];
                    float b0 = acc[mt][nt][2], b1 = acc[mt][nt][3];
                    if (sel < 2) {
                        const int pair = (c & 127) >> 1;
                        float2 t0 = tab[(r0 & (S_LEN - 1)) * 64 + pair];
                        float2 t1 = tab[(r1 & (S_LEN - 1)) * 64 + pair];
                        float rx0 = a0 * t0.x - a1 * t0.y;
                        float ry0 = a0 * t0.y + a1 * t0.x;
                        float rx1 = b0 * t1.x - b1 * t1.y;
                        float ry1 = b0 * t1.y + b1 * t1.x;
                        a0 = rx0; a1 = ry0; b0 = rx1; b1 = ry1;
                    }
                    uint32_t h0 = pk_hi(a0, a1), l0 = pk_lo(a0, a1, h0);
                    uint32_t h1 = pk_hi(b0, b1), l1 = pk_lo(b0, b1, h1);
                    const size_t p0 = ((size_t)r0 * D_DIM + c) >> 1;
                    const size_t p1 = ((size_t)r1 * D_DIM + c) >> 1;
                    ((uint32_t*)H)[p0] = h0;
                    ((uint32_t*)L)[p0] = l0;
                    ((uint32_t*)H)[p1] = h1;
                    ((uint32_t*)L)[p1] = l1;
                }
            }
        }

        tile = next_tile;
    }
}

// ---------------------------------------------------------------------------
// Flash attention, HMMA bf16 hi/lo (unchanged from R11)
// ---------------------------------------------------------------------------
#define FPITCH 272
#define FQ_B   (128 * FPITCH)
#define FKV_A  (64 * FPITCH)
#define SQH_O  0
#define SQL_O  FQ_B
#define SKV_O  (2 * FQ_B)
#define KV_STAGE_B (4 * FKV_A)
#define FLASH_SMEM (2 * FQ_B + 2 * KV_STAGE_B)

__device__ __forceinline__ void f_load_kv(
    uint32_t st, const __nv_bfloat16* __restrict__ Kh,
    const __nv_bfloat16* __restrict__ Kl, const __nv_bfloat16* __restrict__ Vh,
    const __nv_bfloat16* __restrict__ Vl, size_t base, int kb, int tid)
{
#pragma unroll
    for (int it = 0; it < 16; it++) {
        int c = tid + it * 256;
        int arr = c >> 10;
        int r   = (c >> 4) & 63;
        int ch  = c & 15;
        uint32_t dst = st + arr * FKV_A + r * FPITCH + ch * 16;
        const __nv_bfloat16* src;
        size_t ge = base + (size_t)(kb + r) * D_DIM + ch * 8;
        if (arr == 0)      src = Kh + ge;
        else if (arr == 1) src = Kl + ge;
        else if (arr == 2) src = Vh + ge;
        else               src = Vl + ge;
        cp16(dst, src);
    }
}

__global__ void __launch_bounds__(256, 1)
flash_mma_kernel(const __nv_bfloat16* __restrict__ Qh,
                 const __nv_bfloat16* __restrict__ Ql,
                 const __nv_bfloat16* __restrict__ Kh,
                 const __nv_bfloat16* __restrict__ Kl,
                 const __nv_bfloat16* __restrict__ Vh,
                 const __nv_bfloat16* __restrict__ Vl,
                 __nv_bfloat16* __restrict__ OH,
                 __nv_bfloat16* __restrict__ OL)
{
    extern __shared__ char smc[];
    const uint32_t sb = smem_u32(smc);

    const int tid  = threadIdx.x;
    const int wid  = tid >> 5;
    const int lane = tid & 31;
    const int bh = blockIdx.x;
    const int b  = bh >> 4;
    const int h  = bh & 15;
    const int qt = (int)gridDim.y - 1 - (int)blockIdx.y;
    const int q0 = qt * 128;
    const size_t base = (size_t)b * S_LEN * D_DIM + (size_t)h * HD;
    const int nkt = 2 * (qt + 1);

#pragma unroll
    for (int it = 0; it < 16; it++) {
        int c = tid + it * 256;
        int arr = c >> 11;
        int r   = (c >> 4) & 127;
        int ch  = c & 15;
        uint32_t dst = sb + (arr ? SQL_O : SQH_O) + r * FPITCH + ch * 16;
        const __nv_bfloat16* src = (arr ? Ql : Qh)
                                   + base + (size_t)(q0 + r) * D_DIM + ch * 8;
        cp16(dst, src);
    }
    f_load_kv(sb + SKV_O, Kh, Kl, Vh, Vl, base, 0, tid);
    CP_COMMIT();

    const int wrow = wid * 16;
    float o[16][4];
#pragma unroll
    for (int nt = 0; nt < 16; nt++)
#pragma unroll
        for (int e = 0; e < 4; e++) o[nt][e] = 0.f;
    float m0 = -1e30f, m1 = -1e30f, l0 = 0.f, l1 = 0.f;
    const float sc = 0.08838834764831845f * 1.4426950408889634f;
    const unsigned FULL = 0xffffffffu;

    for (int t = 0; t < nkt; t++) {
        const uint32_t st = sb + SKV_O + (t & 1) * KV_STAGE_B;
        if (t + 1 < nkt) {
            f_load_kv(sb + SKV_O + ((t + 1) & 1) * KV_STAGE_B,
                      Kh, Kl, Vh, Vl, base, (t + 1) * 64, tid);
            CP_COMMIT();
            CP_WAIT(1);
        } else {
            CP_WAIT(0);
        }
        __syncthreads();

        const uint32_t KHs = st;
        const uint32_t KLs = st + FKV_A;
        const uint32_t VHs = st + 2 * FKV_A;
        const uint32_t VLs = st + 3 * FKV_A;
        const int kb = t * 64;

        float s[8][4];
#pragma unroll
        for (int nt = 0; nt < 8; nt++)
#pragma unroll
            for (int e = 0; e < 4; e++) s[nt][e] = 0.f;

#pragma unroll
        for (int kk = 0; kk < 8; kk++) {
            uint32_t aoff = (uint32_t)(wrow + (lane & 15)) * FPITCH
                            + (uint32_t)(kk * 16 + (lane >> 4) * 8) * 2;
            uint32_t ah[4], al[4];
            ldsm_x4(ah, sb + SQH_O + aoff);
            ldsm_x4(al, sb + SQL_O + aoff);
            uint32_t bh4[4][4], bl4[4][4];
#pragma unroll
            for (int np = 0; np < 4; np++) {
                uint32_t boff = (uint32_t)(np * 16 + (lane & 7) + ((lane >> 4) << 3)) * FPITCH
                                + (uint32_t)(kk * 16 + (((lane >> 3) & 1) << 3)) * 2;
                ldsm_x4(bh4[np], KHs + boff);
                ldsm_x4(bl4[np], KLs + boff);
            }
#pragma unroll
            for (int np = 0; np < 4; np++) {
                mma16816(s[2 * np],     ah, bh4[np]);
                mma16816(s[2 * np + 1], ah, bh4[np] + 2);
            }
#pragma unroll
            for (int np = 0; np < 4; np++) {
                mma16816(s[2 * np],     ah, bl4[np]);
                mma16816(s[2 * np + 1], ah, bl4[np] + 2);
            }
#pragma unroll
            for (int np = 0; np < 4; np++) {
                mma16816(s[2 * np],     al, bh4[np]);
                mma16816(s[2 * np + 1], al, bh4[np] + 2);
            }
        }

        if (t + 2 >= nkt) {
            const int row0 = q0 + wrow + (lane >> 2);
            const int row1 = row0 + 8;
            const int cbse = kb + ((lane & 3) << 1);
#pragma unroll
            for (int nt = 0; nt < 8; nt++) {
                const int c = cbse + nt * 8;
                if (c     > row0) s[nt][0] = -1e30f;
                if (c + 1 > row0) s[nt][1] = -1e30f;
                if (c     > row1) s[nt][2] = -1e30f;
                if (c + 1 > row1) s[nt][3] = -1e30f;
            }
        }
        float mx0 = -1e30f, mx1 = -1e30f;
#pragma unroll
        for (int nt = 0; nt < 8; nt++) {
            mx0 = fmaxf(mx0, fmaxf(s[nt][0], s[nt][1]));
            mx1 = fmaxf(mx1, fmaxf(s[nt][2], s[nt][3]));
        }
        mx0 = fmaxf(mx0, __shfl_xor_sync(FULL, mx0, 1));
        mx0 = fmaxf(mx0, __shfl_xor_sync(FULL, mx0, 2));
        mx1 = fmaxf(mx1, __shfl_xor_sync(FULL, mx1, 1));
        mx1 = fmaxf(mx1, __shfl_xor_sync(FULL, mx1, 2));
        const float mn0 = fmaxf(m0, mx0);
        const float mn1 = fmaxf(m1, mx1);
        const float cr0 = ex2((m0 - mn0) * sc);
        const float cr1 = ex2((m1 - mn1) * sc);
        m0 = mn0; m1 = mn1;
        float rs0 = 0.f, rs1 = 0.f;
#pragma unroll
        for (int nt = 0; nt < 8; nt++) {
            s[nt][0] = ex2((s[nt][0] - mn0) * sc);
            s[nt][1] = ex2((s[nt][1] - mn0) * sc);
            s[nt][2] = ex2((s[nt][2] - mn1) * sc);
            s[nt][3] = ex2((s[nt][3] - mn1) * sc);
            rs0 += s[nt][0] + s[nt][1];
            rs1 += s[nt][2] + s[nt][3];
        }
        rs0 += __shfl_xor_sync(FULL, rs0, 1);
        rs0 += __shfl_xor_sync(FULL, rs0, 2);
        rs1 += __shfl_xor_sync(FULL, rs1, 1);
        rs1 += __shfl_xor_sync(FULL, rs1, 2);
        l0 = l0 * cr0 + rs0;
        l1 = l1 * cr1 + rs1;
#pragma unroll
        for (int nt = 0; nt < 16; nt++) {
            o[nt][0] *= cr0; o[nt][1] *= cr0;
            o[nt][2] *= cr1; o[nt][3] *= cr1;
        }

        uint32_t ph[4][4], pl[4][4];
#pragma unroll
        for (int j = 0; j < 4; j++) {
            ph[j][0] = pk_hi(s[2 * j][0],     s[2 * j][1]);
            ph[j][1] = pk_hi(s[2 * j][2],     s[2 * j][3]);
            ph[j][2] = pk_hi(s[2 * j + 1][0], s[2 * j + 1][1]);
            ph[j][3] = pk_hi(s[2 * j + 1][2], s[2 * j + 1][3]);
            pl[j][0] = pk_lo(s[2 * j][0],     s[2 * j][1],     ph[j][0]);
            pl[j][1] = pk_lo(s[2 * j][2],     s[2 * j][3],     ph[j][1]);
            pl[j][2] = pk_lo(s[2 * j + 1][0], s[2 * j + 1][1], ph[j][2]);
            pl[j][3] = pk_lo(s[2 * j + 1][2], s[2 * j + 1][3], ph[j][3]);
        }

#pragma unroll
        for (int j = 0; j < 4; j++) {
#pragma unroll
            for (int nd2 = 0; nd2 < 4; nd2++) {
                const int nd0 = nd2 * 2;
                const int nd1 = nd0 + 1;
                uint32_t boff0 = (uint32_t)(j * 16 + (lane & 7) + (((lane >> 3) & 1) << 3)) * FPITCH
                                 + (uint32_t)(nd0 * 16 + ((lane >> 4) << 3)) * 2;
                uint32_t boff1 = boff0 + 32;
                uint32_t vh0[4], vl0[4], vh1[4], vl1[4];
                ldsm_x4_t(vh0, VHs + boff0);
                ldsm_x4_t(vl0, VLs + boff0);
                ldsm_x4_t(vh1, VHs + boff1);
                ldsm_x4_t(vl1, VLs + boff1);
                mma16816(o[2 * nd0],     ph[j], vh0);
                mma16816(o[2 * nd0 + 1], ph[j], vh0 + 2);
                mma16816(o[2 * nd1],     ph[j], vh1);
                mma16816(o[2 * nd1 + 1], ph[j], vh1 + 2);
                mma16816(o[2 * nd0],     ph[j], vl0);
                mma16816(o[2 * nd0 + 1], ph[j], vl0 + 2);
                mma16816(o[2 * nd1],     ph[j], vl1);
                mma16816(o[2 * nd1 + 1], ph[j], vl1 + 2);
                mma16816(o[2 * nd0],     pl[j], vh0);
                mma16816(o[2 * nd0 + 1], pl[j], vh0 + 2);
                mma16816(o[2 * nd1],     pl[j], vh1);
                mma16816(o[2 * nd1 + 1], pl[j], vh1 + 2);
            }
        }
        __syncthreads();
    }

    const float i0 = 1.f / l0;
    const float i1 = 1.f / l1;
    const int r0 = q0 + wrow + (lane >> 2);
    const int r1 = r0 + 8;
#pragma unroll
    for (int nt = 0; nt < 16; nt++) {
        const int col = nt * 8 + ((lane & 3) << 1);
        float a0 = o[nt][0] * i0, a1 = o[nt][1] * i0;
        float b0 = o[nt][2] * i1, b1 = o[nt][3] * i1;
        uint32_t h0 = pk_hi(a0, a1), L0 = pk_lo(a0, a1, h0);
        uint32_t h1 = pk_hi(b0, b1), L1 = pk_lo(b0, b1, h1);
        const size_t p0 = (base + (size_t)r0 * D_DIM + col) >> 1;
        const size_t p1 = (base + (size_t)r1 * D_DIM + col) >> 1;
        ((uint32_t*)OH)[p0] = h0;
        ((uint32_t*)OL)[p0] = L0;
        ((uint32_t*)OH)[p1] = h1;
        ((uint32_t*)OL)[p1] = L1;
    }
}

// ---------------------------------------------------------------------------
// Launcher
// ---------------------------------------------------------------------------
extern "C" void kernel_launch(void* const* d_in, const int* in_sizes, int n_in,
                              void* d_out, int out_size)
{
    const float* x  = (const float*)d_in[0];
    const float* Wq = (const float*)d_in[1];
    const float* Wk = (const float*)d_in[2];
    const float* Wv = (const float*)d_in[3];
    const float* Wo = (const float*)d_in[4];
    float* out = (float*)d_out;

    __nv_bfloat16 *ahi, *alo, *w3hi, *w3lo, *whi, *wlo, *qh, *ql, *kh, *kl, *vh, *vl;
    float2* tab;
    cudaGetSymbolAddress((void**)&ahi,  g_ahi);
    cudaGetSymbolAddress((void**)&alo,  g_alo);
    cudaGetSymbolAddress((void**)&w3hi, g_w3hi);
    cudaGetSymbolAddress((void**)&w3lo, g_w3lo);
    cudaGetSymbolAddress((void**)&whi,  g_whi);
    cudaGetSymbolAddress((void**)&wlo,  g_wlo);
    cudaGetSymbolAddress((void**)&qh,   g_qh);
    cudaGetSymbolAddress((void**)&ql,   g_ql);
    cudaGetSymbolAddress((void**)&kh,   g_kh);
    cudaGetSymbolAddress((void**)&kl,   g_kl);
    cudaGetSymbolAddress((void**)&vh,   g_vh);
    cudaGetSymbolAddress((void**)&vl,   g_vl);
    cudaGetSymbolAddress((void**)&tab,  g_tab);

    cudaFuncSetAttribute(mma_gemm_kernel<0>,
                         cudaFuncAttributeMaxDynamicSharedMemorySize, GEMM_SMEM);
    cudaFuncSetAttribute(mma_gemm_kernel<1>,
                         cudaFuncAttributeMaxDynamicSharedMemorySize, GEMM_SMEM);
    cudaFuncSetAttribute(flash_mma_kernel,
                         cudaFuncAttributeMaxDynamicSharedMemorySize, FLASH_SMEM);

    const int nx4 = (M_ROWS * D_DIM) / 4;
    const int nw4 = (D_DIM * D_DIM) / 4;

    // RoPE table + input split + all-weights split
    tab_kernel<<<(S_LEN * 64 + 255) / 256, 256>>>(tab);
    split_kernel<<<(nx4 + 255) / 256, 256>>>(x, ahi, alo, nx4);
    wsplit4_kernel<<<(4 * nw4 + 255) / 256, 256>>>(Wq, Wk, Wv, Wo,
                                                   w3hi, w3lo, whi, wlo, nw4);

    // Fused QKV projection + rope/split epilogue (pipelined persistent)
    {
        const int nxt = 3 * D_DIM / BN;              // 48
        const int ntiles = nxt * (M_ROWS / BM);      // 1536
        const int grid = (ntiles < GEMM_GRID) ? ntiles : GEMM_GRID;
        mma_gemm_kernel<1><<<grid, 128, GEMM_SMEM>>>(
            ahi, alo, w3hi, w3lo, nullptr,
            qh, ql, kh, kl, vh, vl, tab, M_ROWS, 3 * D_DIM, D_DIM,
            ntiles, nxt);
    }

    // Flash attention -> ctx bf16 hi/lo (reuses ahi/alo buffers)
    dim3 flash_grid(B_SZ * H_NUM, S_LEN / 128);   // (32, 16)
    flash_mma_kernel<<<flash_grid, 256, FLASH_SMEM>>>(qh, ql, kh, kl, vh, vl,
                                                      ahi, alo);

    // Output projection (fp32 epilogue to d_out, pipelined persistent)
    {
        const int nxt = D_DIM / BN;                  // 16
        const int ntiles = nxt * (M_ROWS / BM);      // 512
        const int grid = (ntiles < GEMM_GRID) ? ntiles : GEMM_GRID;
        mma_gemm_kernel<0><<<grid, 128, GEMM_SMEM>>>(
            ahi, alo, whi, wlo, out,
            nullptr, nullptr, nullptr, nullptr, nullptr, nullptr, nullptr,
            M_ROWS, D_DIM, D_DIM, ntiles, nxt);
    }
}

// round 15
// speedup vs baseline: 1.3061x; 1.3061x over previous
#include <cuda_runtime.h>
#include <cuda_fp16.h>
#include <math.h>
#include <cstdint>

// Problem constants
#define B_SZ   2
#define S_LEN  2048
#define D_DIM  2048
#define H_NUM  16
#define HD     128
#define M_ROWS (B_SZ * S_LEN)   // 4096

// ---------------------------------------------------------------------------
// Scratch (static device globals) — fp16
// ---------------------------------------------------------------------------
__device__ __half g_ahi[M_ROWS * D_DIM];        // x hi, later ctx hi
__device__ __half g_alo[M_ROWS * D_DIM];        // x lo, later ctx lo
__device__ __half g_w3h[3 * D_DIM * D_DIM];     // [Wq;Wk;Wv] hi only
__device__ __half g_woh[D_DIM * D_DIM];         // Wo hi only
__device__ __half g_qh [M_ROWS * D_DIM];
__device__ __half g_ql [M_ROWS * D_DIM];
__device__ __half g_kh [M_ROWS * D_DIM];
__device__ __half g_kl [M_ROWS * D_DIM];
__device__ __half g_vh [M_ROWS * D_DIM];
__device__ float2 g_tab[S_LEN * 64];            // rope (cos,sin) table

// ---------------------------------------------------------------------------
// PTX helpers
// ---------------------------------------------------------------------------
__device__ __forceinline__ uint32_t smem_u32(const void* p) {
    uint32_t a;
    asm("{ .reg .u64 t; cvta.to.shared.u64 t, %1; cvt.u32.u64 %0, t; }"
        : "=r"(a) : "l"(p));
    return a;
}
__device__ __forceinline__ void cp16(uint32_t s, const void* g) {
    asm volatile("cp.async.cg.shared.global [%0], [%1], 16;" :: "r"(s), "l"(g));
}
#define CP_COMMIT() asm volatile("cp.async.commit_group;" ::: "memory")
#define CP_WAIT(n)  asm volatile("cp.async.wait_group %0;" :: "n"(n) : "memory")

__device__ __forceinline__ void ldsm_x4(uint32_t* r, uint32_t addr) {
    asm volatile("ldmatrix.sync.aligned.m8n8.x4.shared.b16 {%0,%1,%2,%3}, [%4];"
                 : "=r"(r[0]), "=r"(r[1]), "=r"(r[2]), "=r"(r[3]) : "r"(addr));
}
__device__ __forceinline__ void ldsm_x4_t(uint32_t* r, uint32_t addr) {
    asm volatile("ldmatrix.sync.aligned.m8n8.x4.trans.shared.b16 {%0,%1,%2,%3}, [%4];"
                 : "=r"(r[0]), "=r"(r[1]), "=r"(r[2]), "=r"(r[3]) : "r"(addr));
}
__device__ __forceinline__ void mma16816(float* d, const uint32_t* a,
                                         const uint32_t* b) {
    asm volatile(
        "mma.sync.aligned.m16n8k16.row.col.f32.f16.f16.f32 "
        "{%0,%1,%2,%3}, {%4,%5,%6,%7}, {%8,%9}, {%0,%1,%2,%3};"
        : "+f"(d[0]), "+f"(d[1]), "+f"(d[2]), "+f"(d[3])
        : "r"(a[0]), "r"(a[1]), "r"(a[2]), "r"(a[3]), "r"(b[0]), "r"(b[1]));
}
__device__ __forceinline__ float ex2(float x) {
    float y;
    asm("ex2.approx.ftz.f32 %0, %1;" : "=f"(y) : "f"(x));
    return y;
}
__device__ __forceinline__ uint32_t pk_hi(float a, float b) {
    __half2 t = __floats2half2_rn(a, b);
    return *(uint32_t*)&t;
}
__device__ __forceinline__ uint32_t pk_lo(float a, float b, uint32_t hi) {
    __half2 h = *(__half2*)&hi;
    return pk_hi(a - __half2float(h.x), b - __half2float(h.y));
}

// ---------------------------------------------------------------------------
// RoPE table
// ---------------------------------------------------------------------------
__global__ void tab_kernel(float2* __restrict__ T)
{
    int idx = blockIdx.x * blockDim.x + threadIdx.x;
    if (idx >= S_LEN * 64) return;
    int s = idx >> 6;
    int i = idx & 63;
    float inv = powf(10000.f, -(float)(2 * i) / 128.f);
    float ang = (float)s * inv;
    float sv, cv;
    sincosf(ang, &sv, &cv);
    T[idx] = make_float2(cv, sv);
}

// ---------------------------------------------------------------------------
// split: fp32 -> (hi fp16, lo fp16)
// ---------------------------------------------------------------------------
__global__ void split_kernel(const float* __restrict__ X,
                             __half* __restrict__ H,
                             __half* __restrict__ L, int n4)
{
    int i = blockIdx.x * blockDim.x + threadIdx.x;
    if (i >= n4) return;
    float4 v = ((const float4*)X)[i];
    uint32_t h0 = pk_hi(v.x, v.y), h1 = pk_hi(v.z, v.w);
    uint32_t l0 = pk_lo(v.x, v.y, h0), l1 = pk_lo(v.z, v.w, h1);
    ((uint2*)H)[i] = make_uint2(h0, h1);
    ((uint2*)L)[i] = make_uint2(l0, l1);
}

// ---------------------------------------------------------------------------
// wsplit: round all four weight matrices to fp16 (hi only), one launch.
// ---------------------------------------------------------------------------
__global__ void wsplit_kernel(const float* __restrict__ Wq,
                              const float* __restrict__ Wk,
                              const float* __restrict__ Wv,
                              const float* __restrict__ Wo,
                              __half* __restrict__ W3H,
                              __half* __restrict__ WOH,
                              int nw4)
{
    int i = blockIdx.x * blockDim.x + threadIdx.x;
    if (i >= 4 * nw4) return;
    int sel = i / nw4;
    int j   = i - sel * nw4;
    const float* src = (sel == 0) ? Wq : (sel == 1) ? Wk : (sel == 2) ? Wv : Wo;
    float4 v = ((const float4*)src)[j];
    uint2 h = make_uint2(pk_hi(v.x, v.y), pk_hi(v.z, v.w));
    if (sel < 3) ((uint2*)W3H)[sel * nw4 + j] = h;
    else         ((uint2*)WOH)[j] = h;
}

// ---------------------------------------------------------------------------
// HMMA fp16 2-pass GEMM: C = (Ah+Al) @ Bh^T, fp32 accum.
// 128x128 CTA tile, 4 warps (2x2) of 64x64, 2 CTAs/SM, double buffered.
// MODE 0: fp32 C out. MODE 1: fused QKV epilogue (rope for q/k; v hi only).
// ---------------------------------------------------------------------------
#define BM 128
#define BN 128
#define BK 32
#define PIT 40
#define TILE_B (BM * PIT * 2)        // 10240 bytes per array
#define STAGE_B (3 * TILE_B)         // 30720 (Ah, Al, Bh)
#define GEMM_SMEM (2 * STAGE_B)      // 61440

__device__ __forceinline__ void g_load_stage(
    uint32_t st, const __half* __restrict__ Ah, const __half* __restrict__ Al,
    const __half* __restrict__ Bh, int bm, int bn, int k0, int K, int tid)
{
    // 1536 chunks of 16B: Ah 512, Al 512, Bh 512
#pragma unroll
    for (int it = 0; it < 12; it++) {
        int c = tid + it * 128;
        int arr = c >> 9;
        int r   = (c & 511) >> 2;
        int c16 = c & 3;
        uint32_t dst = st + arr * TILE_B + r * (PIT * 2) + c16 * 16;
        const __half* src;
        if (arr == 0)      src = Ah + (size_t)(bm + r) * K + k0 + c16 * 8;
        else if (arr == 1) src = Al + (size_t)(bm + r) * K + k0 + c16 * 8;
        else               src = Bh + (size_t)(bn + r) * K + k0 + c16 * 8;
        cp16(dst, src);
    }
}

template <int MODE>
__global__ void __launch_bounds__(128, 2)
mma_gemm_kernel(const __half* __restrict__ Ah, const __half* __restrict__ Al,
                const __half* __restrict__ Bh,
                float* __restrict__ C,
                __half* __restrict__ QH, __half* __restrict__ QL,
                __half* __restrict__ KH, __half* __restrict__ KL,
                __half* __restrict__ VH,
                const float2* __restrict__ tab,
                int M, int N, int K)
{
    extern __shared__ char smem[];
    const uint32_t sb = smem_u32(smem);

    const int tid  = threadIdx.x;
    const int wid  = tid >> 5;
    const int lane = tid & 31;
    const int wy   = wid >> 1;
    const int wx   = wid & 1;
    const int bm = blockIdx.y * BM;
    const int bn = blockIdx.x * BN;

    float acc[4][8][4];
#pragma unroll
    for (int mt = 0; mt < 4; mt++)
#pragma unroll
        for (int nt = 0; nt < 8; nt++)
#pragma unroll
            for (int e = 0; e < 4; e++) acc[mt][nt][e] = 0.f;

    const int a_row = wy * 64 + (lane & 15);
    const int a_kof = (lane >> 4) * 8;
    const int b_row = wx * 64 + (lane & 7) + ((lane >> 4) << 3);
    const int b_kof = ((lane >> 3) & 1) * 8;

    const int nk = K / BK;

    g_load_stage(sb, Ah, Al, Bh, bm, bn, 0, K, tid);
    CP_COMMIT();

    for (int i = 0; i < nk; i++) {
        const uint32_t st = sb + (i & 1) * STAGE_B;
        if (i + 1 < nk) {
            g_load_stage(sb + ((i + 1) & 1) * STAGE_B,
                         Ah, Al, Bh, bm, bn, (i + 1) * BK, K, tid);
            CP_COMMIT();
            CP_WAIT(1);
        } else {
            CP_WAIT(0);
        }
        __syncthreads();

        const uint32_t sAh = st;
        const uint32_t sAl = st + TILE_B;
        const uint32_t sBh = st + 2 * TILE_B;

#pragma unroll
        for (int ks = 0; ks < 2; ks++) {
            const int kk = ks * 16;
            uint32_t fah[4][4], fal[4][4], fbh[4][4];
#pragma unroll
            for (int mt = 0; mt < 4; mt++) {
                uint32_t off = (uint32_t)(a_row + mt * 16) * (PIT * 2)
                               + (uint32_t)(kk + a_kof) * 2;
                ldsm_x4(fah[mt], sAh + off);
                ldsm_x4(fal[mt], sAl + off);
            }
#pragma unroll
            for (int np = 0; np < 4; np++) {
                uint32_t off = (uint32_t)(b_row + np * 16) * (PIT * 2)
                               + (uint32_t)(kk + b_kof) * 2;
                ldsm_x4(fbh[np], sBh + off);
            }
#pragma unroll
            for (int mt = 0; mt < 4; mt++)
#pragma unroll
                for (int np = 0; np < 4; np++) {
                    mma16816(acc[mt][2 * np],     fah[mt], fbh[np]);
                    mma16816(acc[mt][2 * np + 1], fah[mt], fbh[np] + 2);
                    mma16816(acc[mt][2 * np],     fal[mt], fbh[np]);
                    mma16816(acc[mt][2 * np + 1], fal[mt], fbh[np] + 2);
                }
        }
        __syncthreads();
    }

    const int er = lane >> 2;
    const int ec = (lane & 3) * 2;

    if (MODE == 0) {
#pragma unroll
        for (int mt = 0; mt < 4; mt++) {
            const int r0 = bm + wy * 64 + mt * 16 + er;
#pragma unroll
            for (int nt = 0; nt < 8; nt++) {
                const int c0 = bn + wx * 64 + nt * 8 + ec;
                *(float2*)&C[(size_t)r0 * N + c0] =
                    make_float2(acc[mt][nt][0], acc[mt][nt][1]);
                *(float2*)&C[(size_t)(r0 + 8) * N + c0] =
                    make_float2(acc[mt][nt][2], acc[mt][nt][3]);
            }
        }
    } else {
        const int sel = bn >> 11;                 // 0=q, 1=k, 2=v (CTA-uniform)
        __half* H = (sel == 0) ? QH : (sel == 1) ? KH : VH;
        __half* L = (sel == 0) ? QL : KL;         // unused when sel==2
#pragma unroll
        for (int mt = 0; mt < 4; mt++) {
            const int r0 = bm + wy * 64 + mt * 16 + er;
            const int r1 = r0 + 8;
#pragma unroll
            for (int nt = 0; nt < 8; nt++) {
                const int c = (bn + wx * 64 + nt * 8 + ec) & 2047;
                float a0 = acc[mt][nt][0], a1 = acc[mt][nt][1];
                float b0 = acc[mt][nt][2], b1 = acc[mt][nt][3];
                if (sel < 2) {
                    const int pair = (c & 127) >> 1;
                    float2 t0 = tab[(r0 & (S_LEN - 1)) * 64 + pair];
                    float2 t1 = tab[(r1 & (S_LEN - 1)) * 64 + pair];
                    float rx0 = a0 * t0.x - a1 * t0.y;
                    float ry0 = a0 * t0.y + a1 * t0.x;
                    float rx1 = b0 * t1.x - b1 * t1.y;
                    float ry1 = b0 * t1.y + b1 * t1.x;
                    a0 = rx0; a1 = ry0; b0 = rx1; b1 = ry1;
                }
                uint32_t h0 = pk_hi(a0, a1);
                uint32_t h1 = pk_hi(b0, b1);
                const size_t p0 = ((size_t)r0 * D_DIM + c) >> 1;
                const size_t p1 = ((size_t)r1 * D_DIM + c) >> 1;
                ((uint32_t*)H)[p0] = h0;
                ((uint32_t*)H)[p1] = h1;
                if (sel < 2) {
                    ((uint32_t*)L)[p0] = pk_lo(a0, a1, h0);
                    ((uint32_t*)L)[p1] = pk_lo(b0, b1, h1);
                }
            }
        }
    }
}

// ---------------------------------------------------------------------------
// Flash attention, fp16: QK^T 3-pass (Qh/Ql x Kh/Kl), PV 2-pass (Ph/Pl x Vh).
// Epilogue writes ctx as fp16 hi/lo.
// ---------------------------------------------------------------------------
#define FPITCH 272
#define FQ_B   (128 * FPITCH)
#define FKV_A  (64 * FPITCH)
#define SQH_O  0
#define SQL_O  FQ_B
#define SKV_O  (2 * FQ_B)
#define KV_STAGE_B (3 * FKV_A)                   // Kh, Kl, Vh
#define FLASH_SMEM (2 * FQ_B + 2 * KV_STAGE_B)   // 174080

__device__ __forceinline__ void f_load_kv(
    uint32_t st, const __half* __restrict__ Kh, const __half* __restrict__ Kl,
    const __half* __restrict__ Vh, size_t base, int kb, int tid)
{
    // 3072 chunks: Kh 1024, Kl 1024, Vh 1024
#pragma unroll
    for (int it = 0; it < 12; it++) {
        int c = tid + it * 256;
        int arr = c >> 10;
        int r   = (c >> 4) & 63;
        int ch  = c & 15;
        uint32_t dst = st + arr * FKV_A + r * FPITCH + ch * 16;
        const __half* src;
        size_t ge = base + (size_t)(kb + r) * D_DIM + ch * 8;
        if (arr == 0)      src = Kh + ge;
        else if (arr == 1) src = Kl + ge;
        else               src = Vh + ge;
        cp16(dst, src);
    }
}

__global__ void __launch_bounds__(256, 1)
flash_mma_kernel(const __half* __restrict__ Qh, const __half* __restrict__ Ql,
                 const __half* __restrict__ Kh, const __half* __restrict__ Kl,
                 const __half* __restrict__ Vh,
                 __half* __restrict__ OH, __half* __restrict__ OL)
{
    extern __shared__ char smc[];
    const uint32_t sb = smem_u32(smc);

    const int tid  = threadIdx.x;
    const int wid  = tid >> 5;
    const int lane = tid & 31;
    const int bh = blockIdx.x;
    const int b  = bh >> 4;
    const int h  = bh & 15;
    const int qt = (int)gridDim.y - 1 - (int)blockIdx.y;
    const int q0 = qt * 128;
    const size_t base = (size_t)b * S_LEN * D_DIM + (size_t)h * HD;
    const int nkt = 2 * (qt + 1);

#pragma unroll
    for (int it = 0; it < 16; it++) {
        int c = tid + it * 256;
        int arr = c >> 11;
        int r   = (c >> 4) & 127;
        int ch  = c & 15;
        uint32_t dst = sb + (arr ? SQL_O : SQH_O) + r * FPITCH + ch * 16;
        const __half* src = (arr ? Ql : Qh)
                            + base + (size_t)(q0 + r) * D_DIM + ch * 8;
        cp16(dst, src);
    }
    f_load_kv(sb + SKV_O, Kh, Kl, Vh, base, 0, tid);
    CP_COMMIT();

    const int wrow = wid * 16;
    float o[16][4];
#pragma unroll
    for (int nt = 0; nt < 16; nt++)
#pragma unroll
        for (int e = 0; e < 4; e++) o[nt][e] = 0.f;
    float m0 = -1e30f, m1 = -1e30f, l0 = 0.f, l1 = 0.f;
    const float sc = 0.08838834764831845f * 1.4426950408889634f;
    const unsigned FULL = 0xffffffffu;

    for (int t = 0; t < nkt; t++) {
        const uint32_t st = sb + SKV_O + (t & 1) * KV_STAGE_B;
        if (t + 1 < nkt) {
            f_load_kv(sb + SKV_O + ((t + 1) & 1) * KV_STAGE_B,
                      Kh, Kl, Vh, base, (t + 1) * 64, tid);
            CP_COMMIT();
            CP_WAIT(1);
        } else {
            CP_WAIT(0);
        }
        __syncthreads();

        const uint32_t KHs = st;
        const uint32_t KLs = st + FKV_A;
        const uint32_t VHs = st + 2 * FKV_A;
        const int kb = t * 64;

        float s[8][4];
#pragma unroll
        for (int nt = 0; nt < 8; nt++)
#pragma unroll
            for (int e = 0; e < 4; e++) s[nt][e] = 0.f;

#pragma unroll
        for (int kk = 0; kk < 8; kk++) {
            uint32_t aoff = (uint32_t)(wrow + (lane & 15)) * FPITCH
                            + (uint32_t)(kk * 16 + (lane >> 4) * 8) * 2;
            uint32_t ah[4], al[4];
            ldsm_x4(ah, sb + SQH_O + aoff);
            ldsm_x4(al, sb + SQL_O + aoff);
            uint32_t bh4[4][4], bl4[4][4];
#pragma unroll
            for (int np = 0; np < 4; np++) {
                uint32_t boff = (uint32_t)(np * 16 + (lane & 7) + ((lane >> 4) << 3)) * FPITCH
                                + (uint32_t)(kk * 16 + (((lane >> 3) & 1) << 3)) * 2;
                ldsm_x4(bh4[np], KHs + boff);
                ldsm_x4(bl4[np], KLs + boff);
            }
#pragma unroll
            for (int np = 0; np < 4; np++) {
                mma16816(s[2 * np],     ah, bh4[np]);
                mma16816(s[2 * np + 1], ah, bh4[np] + 2);
            }
#pragma unroll
            for (int np = 0; np < 4; np++) {
                mma16816(s[2 * np],     ah, bl4[np]);
                mma16816(s[2 * np + 1], ah, bl4[np] + 2);
            }
#pragma unroll
            for (int np = 0; np < 4; np++) {
                mma16816(s[2 * np],     al, bh4[np]);
                mma16816(s[2 * np + 1], al, bh4[np] + 2);
            }
        }

        if (t + 2 >= nkt) {
            const int row0 = q0 + wrow + (lane >> 2);
            const int row1 = row0 + 8;
            const int cbse = kb + ((lane & 3) << 1);
#pragma unroll
            for (int nt = 0; nt < 8; nt++) {
                const int c = cbse + nt * 8;
                if (c     > row0) s[nt][0] = -1e30f;
                if (c + 1 > row0) s[nt][1] = -1e30f;
                if (c     > row1) s[nt][2] = -1e30f;
                if (c + 1 > row1) s[nt][3] = -1e30f;
            }
        }
        float mx0 = -1e30f, mx1 = -1e30f;
#pragma unroll
        for (int nt = 0; nt < 8; nt++) {
            mx0 = fmaxf(mx0, fmaxf(s[nt][0], s[nt][1]));
            mx1 = fmaxf(mx1, fmaxf(s[nt][2], s[nt][3]));
        }
        mx0 = fmaxf(mx0, __shfl_xor_sync(FULL, mx0, 1));
        mx0 = fmaxf(mx0, __shfl_xor_sync(FULL, mx0, 2));
        mx1 = fmaxf(mx1, __shfl_xor_sync(FULL, mx1, 1));
        mx1 = fmaxf(mx1, __shfl_xor_sync(FULL, mx1, 2));
        const float mn0 = fmaxf(m0, mx0);
        const float mn1 = fmaxf(m1, mx1);
        const float cr0 = ex2((m0 - mn0) * sc);
        const float cr1 = ex2((m1 - mn1) * sc);
        m0 = mn0; m1 = mn1;
        float rs0 = 0.f, rs1 = 0.f;
#pragma unroll
        for (int nt = 0; nt < 8; nt++) {
            s[nt][0] = ex2((s[nt][0] - mn0) * sc);
            s[nt][1] = ex2((s[nt][1] - mn0) * sc);
            s[nt][2] = ex2((s[nt][2] - mn1) * sc);
            s[nt][3] = ex2((s[nt][3] - mn1) * sc);
            rs0 += s[nt][0] + s[nt][1];
            rs1 += s[nt][2] + s[nt][3];
        }
        rs0 += __shfl_xor_sync(FULL, rs0, 1);
        rs0 += __shfl_xor_sync(FULL, rs0, 2);
        rs1 += __shfl_xor_sync(FULL, rs1, 1);
        rs1 += __shfl_xor_sync(FULL, rs1, 2);
        l0 = l0 * cr0 + rs0;
        l1 = l1 * cr1 + rs1;
#pragma unroll
        for (int nt = 0; nt < 16; nt++) {
            o[nt][0] *= cr0; o[nt][1] *= cr0;
            o[nt][2] *= cr1; o[nt][3] *= cr1;
        }

        uint32_t ph[4][4], pl[4][4];
#pragma unroll
        for (int j = 0; j < 4; j++) {
            ph[j][0] = pk_hi(s[2 * j][0],     s[2 * j][1]);
            ph[j][1] = pk_hi(s[2 * j][2],     s[2 * j][3]);
            ph[j][2] = pk_hi(s[2 * j + 1][0], s[2 * j + 1][1]);
            ph[j][3] = pk_hi(s[2 * j + 1][2], s[2 * j + 1][3]);
            pl[j][0] = pk_lo(s[2 * j][0],     s[2 * j][1],     ph[j][0]);
            pl[j][1] = pk_lo(s[2 * j][2],     s[2 * j][3],     ph[j][1]);
            pl[j][2] = pk_lo(s[2 * j + 1][0], s[2 * j + 1][1], ph[j][2]);
            pl[j][3] = pk_lo(s[2 * j + 1][2], s[2 * j + 1][3], ph[j][3]);
        }

        // PV 2-pass: (Ph + Pl) x Vh
#pragma unroll
        for (int j = 0; j < 4; j++) {
#pragma unroll
            for (int nd2 = 0; nd2 < 4; nd2++) {
                const int nd0 = nd2 * 2;
                const int nd1 = nd0 + 1;
                uint32_t boff0 = (uint32_t)(j * 16 + (lane & 7) + (((lane >> 3) & 1) << 3)) * FPITCH
                                 + (uint32_t)(nd0 * 16 + ((lane >> 4) << 3)) * 2;
                uint32_t boff1 = boff0 + 32;
                uint32_t vh0[4], vh1[4];
                ldsm_x4_t(vh0, VHs + boff0);
                ldsm_x4_t(vh1, VHs + boff1);
                mma16816(o[2 * nd0],     ph[j], vh0);
                mma16816(o[2 * nd0 + 1], ph[j], vh0 + 2);
                mma16816(o[2 * nd1],     ph[j], vh1);
                mma16816(o[2 * nd1 + 1], ph[j], vh1 + 2);
                mma16816(o[2 * nd0],     pl[j], vh0);
                mma16816(o[2 * nd0 + 1], pl[j], vh0 + 2);
                mma16816(o[2 * nd1],     pl[j], vh1);
                mma16816(o[2 * nd1 + 1], pl[j], vh1 + 2);
            }
        }
        __syncthreads();
    }

    const float i0 = 1.f / l0;
    const float i1 = 1.f / l1;
    const int r0 = q0 + wrow + (lane >> 2);
    const int r1 = r0 + 8;
#pragma unroll
    for (int nt = 0; nt < 16; nt++) {
        const int col = nt * 8 + ((lane & 3) << 1);
        float a0 = o[nt][0] * i0, a1 = o[nt][1] * i0;
        float b0 = o[nt][2] * i1, b1 = o[nt][3] * i1;
        uint32_t h0 = pk_hi(a0, a1), L0 = pk_lo(a0, a1, h0);
        uint32_t h1 = pk_hi(b0, b1), L1 = pk_lo(b0, b1, h1);
        const size_t p0 = (base + (size_t)r0 * D_DIM + col) >> 1;
        const size_t p1 = (base + (size_t)r1 * D_DIM + col) >> 1;
        ((uint32_t*)OH)[p0] = h0;
        ((uint32_t*)OL)[p0] = L0;
        ((uint32_t*)OH)[p1] = h1;
        ((uint32_t*)OL)[p1] = L1;
    }
}

// ---------------------------------------------------------------------------
// Launcher
// ---------------------------------------------------------------------------
extern "C" void kernel_launch(void* const* d_in, const int* in_sizes, int n_in,
                              void* d_out, int out_size)
{
    const float* x  = (const float*)d_in[0];
    const float* Wq = (const float*)d_in[1];
    const float* Wk = (const float*)d_in[2];
    const float* Wv = (const float*)d_in[3];
    const float* Wo = (const float*)d_in[4];
    float* out = (float*)d_out;

    __half *ahi, *alo, *w3h, *woh, *qh, *ql, *kh, *kl, *vh;
    float2* tab;
    cudaGetSymbolAddress((void**)&ahi, g_ahi);
    cudaGetSymbolAddress((void**)&alo, g_alo);
    cudaGetSymbolAddress((void**)&w3h, g_w3h);
    cudaGetSymbolAddress((void**)&woh, g_woh);
    cudaGetSymbolAddress((void**)&qh,  g_qh);
    cudaGetSymbolAddress((void**)&ql,  g_ql);
    cudaGetSymbolAddress((void**)&kh,  g_kh);
    cudaGetSymbolAddress((void**)&kl,  g_kl);
    cudaGetSymbolAddress((void**)&vh,  g_vh);
    cudaGetSymbolAddress((void**)&tab, g_tab);

    cudaFuncSetAttribute(mma_gemm_kernel<0>,
                         cudaFuncAttributeMaxDynamicSharedMemorySize, GEMM_SMEM);
    cudaFuncSetAttribute(mma_gemm_kernel<1>,
                         cudaFuncAttributeMaxDynamicSharedMemorySize, GEMM_SMEM);
    cudaFuncSetAttribute(flash_mma_kernel,
                         cudaFuncAttributeMaxDynamicSharedMemorySize, FLASH_SMEM);

    const int nx4 = (M_ROWS * D_DIM) / 4;
    const int nw4 = (D_DIM * D_DIM) / 4;

    // RoPE table + input split + weight rounding
    tab_kernel<<<(S_LEN * 64 + 255) / 256, 256>>>(tab);
    split_kernel<<<(nx4 + 255) / 256, 256>>>(x, ahi, alo, nx4);
    wsplit_kernel<<<(4 * nw4 + 255) / 256, 256>>>(Wq, Wk, Wv, Wo, w3h, woh, nw4);

    // Fused QKV projection + rope/split epilogue
    dim3 qkv_grid(3 * D_DIM / BN, M_ROWS / BM);   // (48, 32)
    mma_gemm_kernel<1><<<qkv_grid, 128, GEMM_SMEM>>>(
        ahi, alo, w3h, nullptr,
        qh, ql, kh, kl, vh, tab, M_ROWS, 3 * D_DIM, D_DIM);

    // Flash attention -> ctx fp16 hi/lo (reuses ahi/alo buffers)
    dim3 flash_grid(B_SZ * H_NUM, S_LEN / 128);   // (32, 16)
    flash_mma_kernel<<<flash_grid, 256, FLASH_SMEM>>>(qh, ql, kh, kl, vh,
                                                      ahi, alo);

    // Output projection (fp32 epilogue to d_out)
    dim3 ggrid(D_DIM / BN, M_ROWS / BM);          // (16, 32)
    mma_gemm_kernel<0><<<ggrid, 128, GEMM_SMEM>>>(
        ahi, alo, woh, out,
        nullptr, nullptr, nullptr, nullptr, nullptr, nullptr,
        M_ROWS, D_DIM, D_DIM);
}